// round 3
// baseline (speedup 1.0000x reference)
#include <cuda_runtime.h>
#include <cuda_bf16.h>
#include <cstdint>

// SpMM scatter: out[row[e]] += val[e] * embeds[col[e]]  (D = 128 fp32)
//
// Strategy: one warp per edge.
//  - all 32 lanes read row/col/val (broadcast loads, 1 L1 line each)
//  - lane l gathers float4 #l of embeds[col]  -> coalesced 512B per warp
//  - lane l does red.global.add.v4.f32 into out[row] (L2-side reduction,
//    4x fewer atomic transactions than scalar atomicAdd)
//
// Both embeds (51MB) and out (51MB) fit in the 126MB L2 -> L2-bandwidth bound.

#define D_FEAT 128
#define VEC_PER_ROW (D_FEAT / 4)   // 32 float4 per row == 1 per lane

__global__ void __launch_bounds__(256)
gcn_spmm_edge_kernel(const int* __restrict__ edge_row,
                     const int* __restrict__ edge_col,
                     const float* __restrict__ edge_val,
                     const float4* __restrict__ embeds,   // [N, 32] float4
                     float* __restrict__ out,             // [N, 128] float
                     int n_edges)
{
    const int warp_id = (blockIdx.x * blockDim.x + threadIdx.x) >> 5;
    const int lane    = threadIdx.x & 31;
    if (warp_id >= n_edges) return;

    const int e = warp_id;
    const int r = edge_row[e];
    const int c = edge_col[e];
    const float v = edge_val[e];

    // coalesced gather of one 512B embedding row
    const float4 f = __ldg(&embeds[(size_t)c * VEC_PER_ROW + lane]);

    const float m0 = v * f.x;
    const float m1 = v * f.y;
    const float m2 = v * f.z;
    const float m3 = v * f.w;

    float* dst = out + (size_t)r * D_FEAT + lane * 4;
    asm volatile("red.global.add.v4.f32 [%0], {%1, %2, %3, %4};"
                 :: "l"(dst), "f"(m0), "f"(m1), "f"(m2), "f"(m3)
                 : "memory");
}

extern "C" void kernel_launch(void* const* d_in, const int* in_sizes, int n_in,
                              void* d_out, int out_size)
{
    const int*   edge_row = (const int*)  d_in[0];
    const int*   edge_col = (const int*)  d_in[1];
    const float* edge_val = (const float*)d_in[2];
    const float4* embeds  = (const float4*)d_in[3];
    float* out = (float*)d_out;

    const int n_edges = in_sizes[0];

    // d_out is poisoned to 0xAA by the harness -> zero it every launch
    cudaMemsetAsync(d_out, 0, (size_t)out_size * sizeof(float), 0);

    // one warp per edge: 256 threads = 8 warps/block
    const int warps_per_block = 256 / 32;
    const int blocks = (n_edges + warps_per_block - 1) / warps_per_block;
    gcn_spmm_edge_kernel<<<blocks, 256>>>(edge_row, edge_col, edge_val,
                                          embeds, out, n_edges);
}

// round 4
// speedup vs baseline: 1.0209x; 1.0209x over previous
#include <cuda_runtime.h>
#include <cuda_bf16.h>
#include <cstdint>

// SpMM scatter: out[row[e]] += val[e] * embeds[col[e]]  (D = 128 fp32)
//
// Strategy: one warp per edge.
//  - all 32 lanes read row/col/val (broadcast loads, 1 L1 line each)
//  - lane l gathers float4 #l of embeds[col]  -> coalesced 512B per warp
//  - lane l does red.global.add.v4.f32 into out[row] (L2-side reduction,
//    4x fewer atomic transactions than scalar atomicAdd)
//
// Both embeds (51MB) and out (51MB) fit in the 126MB L2 -> L2-bandwidth bound.

#define D_FEAT 128
#define VEC_PER_ROW (D_FEAT / 4)   // 32 float4 per row == 1 per lane

__global__ void __launch_bounds__(256)
gcn_spmm_edge_kernel(const int* __restrict__ edge_row,
                     const int* __restrict__ edge_col,
                     const float* __restrict__ edge_val,
                     const float4* __restrict__ embeds,   // [N, 32] float4
                     float* __restrict__ out,             // [N, 128] float
                     int n_edges)
{
    const int warp_id = (blockIdx.x * blockDim.x + threadIdx.x) >> 5;
    const int lane    = threadIdx.x & 31;
    if (warp_id >= n_edges) return;

    const int e = warp_id;
    const int r = edge_row[e];
    const int c = edge_col[e];
    const float v = edge_val[e];

    // coalesced gather of one 512B embedding row
    const float4 f = __ldg(&embeds[(size_t)c * VEC_PER_ROW + lane]);

    const float m0 = v * f.x;
    const float m1 = v * f.y;
    const float m2 = v * f.z;
    const float m3 = v * f.w;

    float* dst = out + (size_t)r * D_FEAT + lane * 4;
    asm volatile("red.global.add.v4.f32 [%0], {%1, %2, %3, %4};"
                 :: "l"(dst), "f"(m0), "f"(m1), "f"(m2), "f"(m3)
                 : "memory");
}

extern "C" void kernel_launch(void* const* d_in, const int* in_sizes, int n_in,
                              void* d_out, int out_size)
{
    const int*   edge_row = (const int*)  d_in[0];
    const int*   edge_col = (const int*)  d_in[1];
    const float* edge_val = (const float*)d_in[2];
    const float4* embeds  = (const float4*)d_in[3];
    float* out = (float*)d_out;

    const int n_edges = in_sizes[0];

    // d_out is poisoned to 0xAA by the harness -> zero it every launch
    cudaMemsetAsync(d_out, 0, (size_t)out_size * sizeof(float), 0);

    // one warp per edge: 256 threads = 8 warps/block
    const int warps_per_block = 256 / 32;
    const int blocks = (n_edges + warps_per_block - 1) / warps_per_block;
    gcn_spmm_edge_kernel<<<blocks, 256>>>(edge_row, edge_col, edge_val,
                                          embeds, out, n_edges);
}

// round 5
// speedup vs baseline: 1.0215x; 1.0007x over previous
#include <cuda_runtime.h>
#include <cuda_bf16.h>
#include <cstdint>

// SpMM scatter: out[row[e]] += val[e] * embeds[col[e]]  (D = 128 fp32)
//
// Strategy: one warp per edge.
//  - all 32 lanes read row/col/val (broadcast loads, 1 L1 line each)
//  - lane l gathers float4 #l of embeds[col]  -> coalesced 512B per warp
//  - lane l does red.global.add.v4.f32 into out[row] (L2-side reduction,
//    4x fewer atomic transactions than scalar atomicAdd)
//
// Both embeds (51MB) and out (51MB) fit in the 126MB L2 -> L2-bandwidth bound.

#define D_FEAT 128
#define VEC_PER_ROW (D_FEAT / 4)   // 32 float4 per row == 1 per lane

__global__ void __launch_bounds__(256)
gcn_spmm_edge_kernel(const int* __restrict__ edge_row,
                     const int* __restrict__ edge_col,
                     const float* __restrict__ edge_val,
                     const float4* __restrict__ embeds,   // [N, 32] float4
                     float* __restrict__ out,             // [N, 128] float
                     int n_edges)
{
    const int warp_id = (blockIdx.x * blockDim.x + threadIdx.x) >> 5;
    const int lane    = threadIdx.x & 31;
    if (warp_id >= n_edges) return;

    const int e = warp_id;
    const int r = edge_row[e];
    const int c = edge_col[e];
    const float v = edge_val[e];

    // coalesced gather of one 512B embedding row
    const float4 f = __ldg(&embeds[(size_t)c * VEC_PER_ROW + lane]);

    const float m0 = v * f.x;
    const float m1 = v * f.y;
    const float m2 = v * f.z;
    const float m3 = v * f.w;

    float* dst = out + (size_t)r * D_FEAT + lane * 4;
    asm volatile("red.global.add.v4.f32 [%0], {%1, %2, %3, %4};"
                 :: "l"(dst), "f"(m0), "f"(m1), "f"(m2), "f"(m3)
                 : "memory");
}

extern "C" void kernel_launch(void* const* d_in, const int* in_sizes, int n_in,
                              void* d_out, int out_size)
{
    const int*   edge_row = (const int*)  d_in[0];
    const int*   edge_col = (const int*)  d_in[1];
    const float* edge_val = (const float*)d_in[2];
    const float4* embeds  = (const float4*)d_in[3];
    float* out = (float*)d_out;

    const int n_edges = in_sizes[0];

    // d_out is poisoned to 0xAA by the harness -> zero it every launch
    cudaMemsetAsync(d_out, 0, (size_t)out_size * sizeof(float), 0);

    // one warp per edge: 256 threads = 8 warps/block
    const int warps_per_block = 256 / 32;
    const int blocks = (n_edges + warps_per_block - 1) / warps_per_block;
    gcn_spmm_edge_kernel<<<blocks, 256>>>(edge_row, edge_col, edge_val,
                                          embeds, out, n_edges);
}

// round 6
// speedup vs baseline: 1.0222x; 1.0007x over previous
#include <cuda_runtime.h>
#include <cuda_bf16.h>
#include <cstdint>

// SpMM scatter: out[row[e]] += val[e] * embeds[col[e]]  (D = 128 fp32)
//
// Strategy: one warp per edge.
//  - all 32 lanes read row/col/val (broadcast loads, 1 L1 line each)
//  - lane l gathers float4 #l of embeds[col]  -> coalesced 512B per warp
//  - lane l does red.global.add.v4.f32 into out[row] (L2-side reduction,
//    4x fewer atomic transactions than scalar atomicAdd)
//
// Both embeds (51MB) and out (51MB) fit in the 126MB L2 -> L2-bandwidth bound.

#define D_FEAT 128
#define VEC_PER_ROW (D_FEAT / 4)   // 32 float4 per row == 1 per lane

__global__ void __launch_bounds__(256)
gcn_spmm_edge_kernel(const int* __restrict__ edge_row,
                     const int* __restrict__ edge_col,
                     const float* __restrict__ edge_val,
                     const float4* __restrict__ embeds,   // [N, 32] float4
                     float* __restrict__ out,             // [N, 128] float
                     int n_edges)
{
    const int warp_id = (blockIdx.x * blockDim.x + threadIdx.x) >> 5;
    const int lane    = threadIdx.x & 31;
    if (warp_id >= n_edges) return;

    const int e = warp_id;
    const int r = edge_row[e];
    const int c = edge_col[e];
    const float v = edge_val[e];

    // coalesced gather of one 512B embedding row
    const float4 f = __ldg(&embeds[(size_t)c * VEC_PER_ROW + lane]);

    const float m0 = v * f.x;
    const float m1 = v * f.y;
    const float m2 = v * f.z;
    const float m3 = v * f.w;

    float* dst = out + (size_t)r * D_FEAT + lane * 4;
    asm volatile("red.global.add.v4.f32 [%0], {%1, %2, %3, %4};"
                 :: "l"(dst), "f"(m0), "f"(m1), "f"(m2), "f"(m3)
                 : "memory");
}

extern "C" void kernel_launch(void* const* d_in, const int* in_sizes, int n_in,
                              void* d_out, int out_size)
{
    const int*   edge_row = (const int*)  d_in[0];
    const int*   edge_col = (const int*)  d_in[1];
    const float* edge_val = (const float*)d_in[2];
    const float4* embeds  = (const float4*)d_in[3];
    float* out = (float*)d_out;

    const int n_edges = in_sizes[0];

    // d_out is poisoned to 0xAA by the harness -> zero it every launch
    cudaMemsetAsync(d_out, 0, (size_t)out_size * sizeof(float), 0);

    // one warp per edge: 256 threads = 8 warps/block
    const int warps_per_block = 256 / 32;
    const int blocks = (n_edges + warps_per_block - 1) / warps_per_block;
    gcn_spmm_edge_kernel<<<blocks, 256>>>(edge_row, edge_col, edge_val,
                                          embeds, out, n_edges);
}